// round 6
// baseline (speedup 1.0000x reference)
#include <cuda_runtime.h>
#include <cuda_bf16.h>
#include <math.h>
#include <stdint.h>

// Problem constants
#define NB    4
#define CIN   1024
#define CINT  512
#define HH    96
#define WW    96
#define PP    (HH * WW)      // 9216
#define DD    4
#define QQ    81
#define CSPLIT 2             // corr channel split
#define ASPLIT 8             // assemble channel split

// ---------------------------------------------------------------------------
// Scratch (device globals; no allocation allowed)
// ---------------------------------------------------------------------------
__device__ __align__(128) __nv_bfloat16 g_wb   [4 * CINT * CIN];   // theta,g,phi,out
__device__ __align__(128) float g_theta [NB * CINT * PP];
__device__ __align__(128) float g_g     [NB * CINT * PP];
__device__ __align__(128) float g_phi   [NB * CINT * PP];
__device__ __align__(128) float g_pwpart[CSPLIT * NB * QQ * PP];
__device__ __align__(128) float g_pw    [NB * QQ * PP];
__device__ __align__(128) __nv_bfloat16 g_yb   [NB * CINT * PP];

// ---------------------------------------------------------------------------
// Helpers (legacy path: cp.async + ldmatrix + mma.sync; no tcgen05 — the
// toolchain targets sm_103 without the 'a' feature set)
// ---------------------------------------------------------------------------
__device__ __forceinline__ uint32_t sptr(const void* p) {
    return (uint32_t)__cvta_generic_to_shared(p);
}
__device__ __forceinline__ void cp16(uint32_t dst, const void* src) {
    asm volatile("cp.async.cg.shared.global [%0], [%1], 16;" :: "r"(dst), "l"(src));
}
__device__ __forceinline__ void cp_commit() {
    asm volatile("cp.async.commit_group;");
}
__device__ __forceinline__ void cp_wait0() {
    asm volatile("cp.async.wait_group 0;");
}
__device__ __forceinline__ void ldsmx4(uint32_t* r, uint32_t addr) {
    asm volatile("ldmatrix.sync.aligned.m8n8.x4.shared.b16 {%0,%1,%2,%3}, [%4];"
                 : "=r"(r[0]), "=r"(r[1]), "=r"(r[2]), "=r"(r[3]) : "r"(addr));
}
__device__ __forceinline__ void ldsmx4t(uint32_t* r, uint32_t addr) {
    asm volatile("ldmatrix.sync.aligned.m8n8.x4.trans.shared.b16 {%0,%1,%2,%3}, [%4];"
                 : "=r"(r[0]), "=r"(r[1]), "=r"(r[2]), "=r"(r[3]) : "r"(addr));
}
__device__ __forceinline__ void mma16816(float* c, const uint32_t* a, const uint32_t* b) {
    asm volatile("mma.sync.aligned.m16n8k16.row.col.f32.bf16.bf16.f32 "
                 "{%0,%1,%2,%3}, {%4,%5,%6,%7}, {%8,%9}, {%0,%1,%2,%3};"
                 : "+f"(c[0]), "+f"(c[1]), "+f"(c[2]), "+f"(c[3])
                 : "r"(a[0]), "r"(a[1]), "r"(a[2]), "r"(a[3]), "r"(b[0]), "r"(b[1]));
}

// Packed f32x2 (Blackwell base ISA): doubles fp32 FMA throughput.
__device__ __forceinline__ unsigned long long pk2(float a, float b) {
    unsigned long long r;
    asm("mov.b64 %0, {%1, %2};" : "=l"(r) : "f"(a), "f"(b));
    return r;
}
__device__ __forceinline__ void fma2(unsigned long long& d,
                                     unsigned long long a, unsigned long long b) {
    asm("fma.rn.f32x2 %0, %1, %2, %0;" : "+l"(d) : "l"(a), "l"(b));
}
__device__ __forceinline__ float2 upk(unsigned long long v) {
    float2 r;
    asm("mov.b64 {%0, %1}, %2;" : "=f"(r.x), "=f"(r.y) : "l"(v));
    return r;
}

// ---------------------------------------------------------------------------
// fp32 -> bf16 conversion (weights only; n multiple of 2048)
// ---------------------------------------------------------------------------
__global__ void __launch_bounds__(256)
f2bf_kernel(const float* __restrict__ in, __nv_bfloat16* __restrict__ out, int n)
{
    int i = (blockIdx.x * 256 + threadIdx.x) * 8;
    if (i >= n) return;
    float4 v0 = *(const float4*)(in + i);
    float4 v1 = *(const float4*)(in + i + 4);
    __nv_bfloat162 o[4];
    o[0] = __floats2bfloat162_rn(v0.x, v0.y);
    o[1] = __floats2bfloat162_rn(v0.z, v0.w);
    o[2] = __floats2bfloat162_rn(v1.x, v1.y);
    o[3] = __floats2bfloat162_rn(v1.z, v1.w);
    *(uint4*)(out + i) = *(const uint4*)o;
}

// ---------------------------------------------------------------------------
// Shared GEMM geometry (BM=BN=128, BK=32, 8 warps 2m x 4n, warp tile 64x32)
// ---------------------------------------------------------------------------
#define AS_STRIDE 40
#define BS_STRIDE 136
#define AS_ELEMS (128 * AS_STRIDE)
#define BS_ELEMS (32 * BS_STRIDE)
#define AS_BYTES (AS_ELEMS * 2)
#define BS_BYTES (BS_ELEMS * 2)

// ---------------------------------------------------------------------------
// GEMM variant A: B operand read as fp32 from global, converted to bf16 in
// registers while staging to smem (kills the x/x_ref f2bf round-trip).
// O[b][m][p] = sum_k W[m][k]*Z[b][k][p] + bias[m]
// ---------------------------------------------------------------------------
__global__ void __launch_bounds__(256)
bgemm_f32b(const __nv_bfloat16* __restrict__ W, const float* __restrict__ Z,
           const float* __restrict__ bias, float* __restrict__ O,
           int M, int K, int P)
{
    __shared__ __align__(16) __nv_bfloat16 As[2 * AS_ELEMS];
    __shared__ __align__(16) __nv_bfloat16 Bs[2 * BS_ELEMS];

    const int b  = blockIdx.z;
    const float* Zb = Z + (size_t)b * K * P;
    float*       Ob = O + (size_t)b * M * P;

    const int m0 = blockIdx.y * 128;
    const int n0 = blockIdx.x * 128;
    const int tid  = threadIdx.x;
    const int lane = tid & 31;
    const int wid  = tid >> 5;
    const int wm = wid & 1;
    const int wn = wid >> 1;

    const uint32_t as0 = sptr(As);
    const uint32_t bs0 = sptr(Bs);

    const int a_r = tid >> 2;
    const int a_c = tid & 3;
    const int brow  = tid >> 3;          // 0..31
    const int bcol0 = (tid & 7) * 16;    // 0..112

    float acc[4][4][4];
#pragma unroll
    for (int mt = 0; mt < 4; mt++)
#pragma unroll
        for (int nt = 0; nt < 4; nt++)
#pragma unroll
            for (int i = 0; i < 4; i++) acc[mt][nt][i] = 0.f;

    const int nk = K >> 5;

    // prologue: cp.async A(0); LDG B(0) into registers
    cp16(as0 + (uint32_t)((a_r)      * AS_STRIDE + a_c * 8) * 2, W + (size_t)(m0 + a_r)      * K + a_c * 8);
    cp16(as0 + (uint32_t)((a_r + 64) * AS_STRIDE + a_c * 8) * 2, W + (size_t)(m0 + a_r + 64) * K + a_c * 8);
    cp_commit();

    float4 pf[4];
    {
        const float* src = Zb + (size_t)brow * P + n0 + bcol0;
#pragma unroll
        for (int j = 0; j < 4; j++) pf[j] = *(const float4*)(src + 4 * j);
    }

    int stage = 0;
    for (int kt = 0; kt < nk; kt++) {
        // store B(kt) regs -> Bs[stage] (convert to bf16)
        {
            __nv_bfloat16* bsp = Bs + stage * BS_ELEMS + brow * BS_STRIDE + bcol0;
#pragma unroll
            for (int j = 0; j < 4; j++) {
                __nv_bfloat162 lo = __floats2bfloat162_rn(pf[j].x, pf[j].y);
                __nv_bfloat162 hi = __floats2bfloat162_rn(pf[j].z, pf[j].w);
                uint2 v;
                v.x = *(uint32_t*)&lo;
                v.y = *(uint32_t*)&hi;
                *(uint2*)&bsp[4 * j] = v;
            }
        }
        cp_wait0();          // A(kt) landed
        __syncthreads();     // Bs[stage] + As[stage] visible

        if (kt + 1 < nk) {
            const int k0 = (kt + 1) * 32;
            const uint32_t as = as0 + (stage ^ 1) * AS_BYTES;
            cp16(as + (uint32_t)((a_r)      * AS_STRIDE + a_c * 8) * 2, W + (size_t)(m0 + a_r)      * K + k0 + a_c * 8);
            cp16(as + (uint32_t)((a_r + 64) * AS_STRIDE + a_c * 8) * 2, W + (size_t)(m0 + a_r + 64) * K + k0 + a_c * 8);
            cp_commit();
            const float* src = Zb + (size_t)(k0 + brow) * P + n0 + bcol0;
#pragma unroll
            for (int j = 0; j < 4; j++) pf[j] = *(const float4*)(src + 4 * j);
        }

        const uint32_t as = as0 + stage * AS_BYTES;
        const uint32_t bs = bs0 + stage * BS_BYTES;

#pragma unroll
        for (int kk = 0; kk < 2; kk++) {
            const int k0 = kk * 16;
            uint32_t a[4][4];
            const uint32_t a_base = as + (uint32_t)(((wm * 64 + (lane & 15)) * AS_STRIDE) + k0 + (lane >> 4) * 8) * 2;
#pragma unroll
            for (int mt = 0; mt < 4; mt++)
                ldsmx4(a[mt], a_base + (uint32_t)(mt * 16 * AS_STRIDE) * 2);

            uint32_t bb[4][2];
            const uint32_t b_base = bs + (uint32_t)((k0 + (lane & 15)) * BS_STRIDE + wn * 32 + (lane >> 4) * 8) * 2;
            {
                uint32_t r[4];
                ldsmx4t(r, b_base);
                bb[0][0] = r[0]; bb[0][1] = r[1];
                bb[1][0] = r[2]; bb[1][1] = r[3];
                ldsmx4t(r, b_base + 16 * 2);
                bb[2][0] = r[0]; bb[2][1] = r[1];
                bb[3][0] = r[2]; bb[3][1] = r[3];
            }

#pragma unroll
            for (int mt = 0; mt < 4; mt++)
#pragma unroll
                for (int nt = 0; nt < 4; nt++)
                    mma16816(acc[mt][nt], a[mt], bb[nt]);
        }
        __syncthreads();
        stage ^= 1;
    }

#pragma unroll
    for (int mt = 0; mt < 4; mt++) {
        const int r0 = m0 + wm * 64 + mt * 16 + (lane >> 2);
        const int r1 = r0 + 8;
        const float bv0 = bias[r0];
        const float bv1 = bias[r1];
#pragma unroll
        for (int nt = 0; nt < 4; nt++) {
            const int col = n0 + wn * 32 + nt * 8 + (lane & 3) * 2;
            float2 v0 = make_float2(acc[mt][nt][0] + bv0, acc[mt][nt][1] + bv0);
            float2 v1 = make_float2(acc[mt][nt][2] + bv1, acc[mt][nt][3] + bv1);
            *(float2*)&Ob[(size_t)r0 * P + col] = v0;
            *(float2*)&Ob[(size_t)r1 * P + col] = v1;
        }
    }
}

// ---------------------------------------------------------------------------
// GEMM variant B: bf16 B operand (final conv; reads y bf16, adds residual)
// ---------------------------------------------------------------------------
__global__ void __launch_bounds__(256)
bgemm_kernel(const __nv_bfloat16* __restrict__ W, const __nv_bfloat16* __restrict__ Z,
             const float* __restrict__ bias, const float* __restrict__ res,
             float* __restrict__ O, int M, int K, int P)
{
    __shared__ __align__(16) __nv_bfloat16 As[2 * AS_ELEMS];
    __shared__ __align__(16) __nv_bfloat16 Bs[2 * BS_ELEMS];

    const int b  = blockIdx.z;
    const __nv_bfloat16* Zb = Z + (size_t)b * K * P;
    float*       Ob = O + (size_t)b * M * P;
    const float* Rb = res + (size_t)b * M * P;

    const int m0 = blockIdx.y * 128;
    const int n0 = blockIdx.x * 128;
    const int tid  = threadIdx.x;
    const int lane = tid & 31;
    const int wid  = tid >> 5;
    const int wm = wid & 1;
    const int wn = wid >> 1;

    const uint32_t as0 = sptr(As);
    const uint32_t bs0 = sptr(Bs);

    const int a_r = tid >> 2;
    const int a_c = tid & 3;
    const int b_r = tid >> 4;
    const int b_c = tid & 15;

    float acc[4][4][4];
#pragma unroll
    for (int mt = 0; mt < 4; mt++)
#pragma unroll
        for (int nt = 0; nt < 4; nt++)
#pragma unroll
            for (int i = 0; i < 4; i++) acc[mt][nt][i] = 0.f;

    const int nk = K >> 5;

    {
        cp16(as0 + (uint32_t)((a_r)      * AS_STRIDE + a_c * 8) * 2, W  + (size_t)(m0 + a_r)      * K + a_c * 8);
        cp16(as0 + (uint32_t)((a_r + 64) * AS_STRIDE + a_c * 8) * 2, W  + (size_t)(m0 + a_r + 64) * K + a_c * 8);
        cp16(bs0 + (uint32_t)((b_r)      * BS_STRIDE + b_c * 8) * 2, Zb + (size_t)(b_r)      * P + n0 + b_c * 8);
        cp16(bs0 + (uint32_t)((b_r + 16) * BS_STRIDE + b_c * 8) * 2, Zb + (size_t)(b_r + 16) * P + n0 + b_c * 8);
        cp_commit();
    }

    int stage = 0;
    for (int kt = 0; kt < nk; kt++) {
        cp_wait0();
        __syncthreads();

        if (kt + 1 < nk) {
            const int k0 = (kt + 1) * 32;
            const uint32_t as = as0 + (stage ^ 1) * AS_BYTES;
            const uint32_t bs = bs0 + (stage ^ 1) * BS_BYTES;
            cp16(as + (uint32_t)((a_r)      * AS_STRIDE + a_c * 8) * 2, W  + (size_t)(m0 + a_r)      * K + k0 + a_c * 8);
            cp16(as + (uint32_t)((a_r + 64) * AS_STRIDE + a_c * 8) * 2, W  + (size_t)(m0 + a_r + 64) * K + k0 + a_c * 8);
            cp16(bs + (uint32_t)((b_r)      * BS_STRIDE + b_c * 8) * 2, Zb + (size_t)(k0 + b_r)      * P + n0 + b_c * 8);
            cp16(bs + (uint32_t)((b_r + 16) * BS_STRIDE + b_c * 8) * 2, Zb + (size_t)(k0 + b_r + 16) * P + n0 + b_c * 8);
            cp_commit();
        }

        const uint32_t as = as0 + stage * AS_BYTES;
        const uint32_t bs = bs0 + stage * BS_BYTES;

#pragma unroll
        for (int kk = 0; kk < 2; kk++) {
            const int k0 = kk * 16;
            uint32_t a[4][4];
            const uint32_t a_base = as + (uint32_t)(((wm * 64 + (lane & 15)) * AS_STRIDE) + k0 + (lane >> 4) * 8) * 2;
#pragma unroll
            for (int mt = 0; mt < 4; mt++)
                ldsmx4(a[mt], a_base + (uint32_t)(mt * 16 * AS_STRIDE) * 2);

            uint32_t bb[4][2];
            const uint32_t b_base = bs + (uint32_t)((k0 + (lane & 15)) * BS_STRIDE + wn * 32 + (lane >> 4) * 8) * 2;
            {
                uint32_t r[4];
                ldsmx4t(r, b_base);
                bb[0][0] = r[0]; bb[0][1] = r[1];
                bb[1][0] = r[2]; bb[1][1] = r[3];
                ldsmx4t(r, b_base + 16 * 2);
                bb[2][0] = r[0]; bb[2][1] = r[1];
                bb[3][0] = r[2]; bb[3][1] = r[3];
            }

#pragma unroll
            for (int mt = 0; mt < 4; mt++)
#pragma unroll
                for (int nt = 0; nt < 4; nt++)
                    mma16816(acc[mt][nt], a[mt], bb[nt]);
        }
        stage ^= 1;
        __syncthreads();
    }

#pragma unroll
    for (int mt = 0; mt < 4; mt++) {
        const int r0 = m0 + wm * 64 + mt * 16 + (lane >> 2);
        const int r1 = r0 + 8;
        const float bv0 = bias[r0];
        const float bv1 = bias[r1];
#pragma unroll
        for (int nt = 0; nt < 4; nt++) {
            const int col = n0 + wn * 32 + nt * 8 + (lane & 3) * 2;
            float2 v0 = make_float2(acc[mt][nt][0] + bv0, acc[mt][nt][1] + bv0);
            float2 v1 = make_float2(acc[mt][nt][2] + bv1, acc[mt][nt][3] + bv1);
            float2 t0 = *(const float2*)&Rb[(size_t)r0 * P + col];
            float2 t1 = *(const float2*)&Rb[(size_t)r1 * P + col];
            v0.x += t0.x; v0.y += t0.y;
            v1.x += t1.x; v1.y += t1.y;
            *(float2*)&Ob[(size_t)r0 * P + col] = v0;
            *(float2*)&Ob[(size_t)r1 * P + col] = v1;
        }
    }
}

// ---------------------------------------------------------------------------
// Correlation, x-pair blocking + packed f32x2 FMA.
// Tile 32(w) x 16(h); thread (tx,ty) owns pixels (ty, 2tx) and (ty, 2tx+1).
// All 81 accumulators packed as f32x2 pairs; window pairs are aligned LDS.64.
// ---------------------------------------------------------------------------
#define CTW 32
#define CTH2 16
#define CWW (CTW + 2 * DD)    // 40
#define CWH (CTH2 + 2 * DD)   // 24
#define CCH 8
#define CPB (CINT / CSPLIT)   // 256

__global__ void __launch_bounds__(256, 1)
corr_kernel(const float* __restrict__ theta,
            const float* __restrict__ phi,
            float* __restrict__ pwpart)
{
    __shared__ float th_s[CCH * CTH2 * CTW];   // 16 KB
    __shared__ float ph_s[CCH * CWH * CWW];    // 30 KB

    const int z  = blockIdx.z;
    const int b  = z >> 1;
    const int ci = z & 1;
    const int ch0 = ci * CPB;
    const int w0 = blockIdx.x * CTW;
    const int h0 = blockIdx.y * CTH2;
    const int tid = threadIdx.x;
    const int tx = tid & 15;          // 16 threads in x, 2 pixels each
    const int ty = tid >> 4;          // 0..15

    const float* thb = theta + (size_t)b * CINT * PP;
    const float* phb = phi   + (size_t)b * CINT * PP;

    unsigned long long P[QQ];
#pragma unroll
    for (int q = 0; q < QQ; q++) P[q] = 0ull;

    for (int c0 = ch0; c0 < ch0 + CPB; c0 += CCH) {
        // theta tile: CCH x 16 x 32 = 4096 floats
#pragma unroll
        for (int ii = 0; ii < (CCH * CTH2 * CTW) / 256; ii++) {
            const int i   = tid + ii * 256;
            const int cc  = i >> 9;
            const int rem = i & 511;
            th_s[i] = thb[(size_t)(c0 + cc) * PP + (h0 + (rem >> 5)) * WW + (w0 + (rem & 31))];
        }
        // phi window: CCH x 24 x 40 = 7680 floats, zero-padded
#pragma unroll
        for (int ii = 0; ii < (CCH * CWH * CWW) / 256; ii++) {
            const int i   = tid + ii * 256;
            const int cc  = i / (CWH * CWW);
            const int rem = i % (CWH * CWW);
            const int r   = rem / CWW;
            const int col = rem % CWW;
            const int hh = h0 - DD + r;
            const int ww = w0 - DD + col;
            float v = 0.f;
            if (hh >= 0 && hh < HH && ww >= 0 && ww < WW)
                v = phb[(size_t)(c0 + cc) * PP + hh * WW + ww];
            ph_s[i] = v;
        }
        __syncthreads();

#pragma unroll
        for (int cc = 0; cc < CCH; cc++) {
            const float2 t2 = *(const float2*)&th_s[cc * (CTH2 * CTW) + ty * CTW + 2 * tx];
            const unsigned long long tp = pk2(t2.x, t2.y);
            const float* pr = &ph_s[cc * (CWH * CWW)];
#pragma unroll
            for (int dy = 0; dy < 9; dy++) {
                const float* row = &pr[(ty + dy) * CWW + 2 * tx];
                const float2 e0 = *(const float2*)&row[0];
                const float2 e1 = *(const float2*)&row[2];
                const float2 e2 = *(const float2*)&row[4];
                const float2 e3 = *(const float2*)&row[6];
                const float2 e4 = *(const float2*)&row[8];
                fma2(P[dy * 9 + 0], tp, pk2(e0.x, e0.y));
                fma2(P[dy * 9 + 1], tp, pk2(e0.y, e1.x));
                fma2(P[dy * 9 + 2], tp, pk2(e1.x, e1.y));
                fma2(P[dy * 9 + 3], tp, pk2(e1.y, e2.x));
                fma2(P[dy * 9 + 4], tp, pk2(e2.x, e2.y));
                fma2(P[dy * 9 + 5], tp, pk2(e2.y, e3.x));
                fma2(P[dy * 9 + 6], tp, pk2(e3.x, e3.y));
                fma2(P[dy * 9 + 7], tp, pk2(e3.y, e4.x));
                fma2(P[dy * 9 + 8], tp, pk2(e4.x, e4.y));
            }
        }
        __syncthreads();
    }

    const int pixA = (h0 + ty) * WW + (w0 + 2 * tx);
    float* bp = pwpart + ((size_t)(ci * NB + b) * QQ) * PP;
#pragma unroll
    for (int q = 0; q < QQ; q++)
        *(float2*)&bp[(size_t)q * PP + pixA] = upk(P[q]);
}

// ---------------------------------------------------------------------------
// Softmax over Q (sums 2 channel-split partials, applies scale)
// ---------------------------------------------------------------------------
__global__ void __launch_bounds__(128)
softmax_kernel(const float* __restrict__ part, float* __restrict__ pw)
{
    const int t = blockIdx.x * 128 + threadIdx.x;
    const int b = t / PP;
    const int pix = t - b * PP;
    const size_t qp = (size_t)QQ * PP;
    const float scale = 256.0f / sqrtf((float)WW) / (float)CINT;

    float v[QQ];
    float m = -1e30f;
#pragma unroll
    for (int q = 0; q < QQ; q++) {
        const size_t off = (size_t)q * PP + pix;
        float s = part[(size_t)(0 * NB + b) * qp + off]
                + part[(size_t)(1 * NB + b) * qp + off];
        v[q] = s * scale;
        m = fmaxf(m, v[q]);
    }
    float s = 0.f;
#pragma unroll
    for (int q = 0; q < QQ; q++) { v[q] = __expf(v[q] - m); s += v[q]; }
    const float inv = 1.0f / s;
    float* pwb = pw + (size_t)b * qp + pix;
#pragma unroll
    for (int q = 0; q < QQ; q++) pwb[(size_t)q * PP] = v[q] * inv;
}

// ---------------------------------------------------------------------------
// Assemble, x-pair blocking + packed f32x2: y = sum_q pw*g_window (bf16 out)
// ---------------------------------------------------------------------------
__global__ void __launch_bounds__(256, 1)
assemble_kernel(const float* __restrict__ pw,
                const float* __restrict__ g,
                __nv_bfloat16* __restrict__ y)
{
    __shared__ float gs[CCH * CWH * CWW];   // 30 KB

    const int z  = blockIdx.z;
    const int b  = z >> 3;
    const int c0base = (z & 7) * (CINT / ASPLIT); // 64 channels
    const int w0 = blockIdx.x * CTW;
    const int h0 = blockIdx.y * CTH2;
    const int tid = threadIdx.x;
    const int tx = tid & 15;
    const int ty = tid >> 4;

    const float* gb  = g  + (size_t)b * CINT * PP;
    const float* pwb = pw + (size_t)b * QQ * PP;
    __nv_bfloat16* yb = y + (size_t)b * CINT * PP;

    const int pixA = (h0 + ty) * WW + (w0 + 2 * tx);

    unsigned long long rp[QQ];
#pragma unroll
    for (int q = 0; q < QQ; q++) {
        const float2 v = *(const float2*)&pwb[(size_t)q * PP + pixA];
        rp[q] = pk2(v.x, v.y);
    }

    for (int c0 = c0base; c0 < c0base + CINT / ASPLIT; c0 += CCH) {
#pragma unroll
        for (int ii = 0; ii < (CCH * CWH * CWW) / 256; ii++) {
            const int i   = tid + ii * 256;
            const int cc  = i / (CWH * CWW);
            const int rem = i % (CWH * CWW);
            const int r   = rem / CWW;
            const int col = rem % CWW;
            const int hh = h0 - DD + r;
            const int ww = w0 - DD + col;
            float v = 0.f;
            if (hh >= 0 && hh < HH && ww >= 0 && ww < WW)
                v = gb[(size_t)(c0 + cc) * PP + hh * WW + ww];
            gs[i] = v;
        }
        __syncthreads();

#pragma unroll
        for (int cc = 0; cc < CCH; cc++) {
            const float* gr = &gs[cc * (CWH * CWW)];
            unsigned long long a2 = 0ull;
#pragma unroll
            for (int dy = 0; dy < 9; dy++) {
                const float* row = &gr[(ty + dy) * CWW + 2 * tx];
                const float2 e0 = *(const float2*)&row[0];
                const float2 e1 = *(const float2*)&row[2];
                const float2 e2 = *(const float2*)&row[4];
                const float2 e3 = *(const float2*)&row[6];
                const float2 e4 = *(const float2*)&row[8];
                fma2(a2, rp[dy * 9 + 0], pk2(e0.x, e0.y));
                fma2(a2, rp[dy * 9 + 1], pk2(e0.y, e1.x));
                fma2(a2, rp[dy * 9 + 2], pk2(e1.x, e1.y));
                fma2(a2, rp[dy * 9 + 3], pk2(e1.y, e2.x));
                fma2(a2, rp[dy * 9 + 4], pk2(e2.x, e2.y));
                fma2(a2, rp[dy * 9 + 5], pk2(e2.y, e3.x));
                fma2(a2, rp[dy * 9 + 6], pk2(e3.x, e3.y));
                fma2(a2, rp[dy * 9 + 7], pk2(e3.y, e4.x));
                fma2(a2, rp[dy * 9 + 8], pk2(e4.x, e4.y));
            }
            const float2 r = upk(a2);
            *(__nv_bfloat162*)&yb[(size_t)(c0 + cc) * PP + pixA] =
                __floats2bfloat162_rn(r.x, r.y);
        }
        __syncthreads();
    }
}

// ---------------------------------------------------------------------------
// Launch
// ---------------------------------------------------------------------------
extern "C" void kernel_launch(void* const* d_in, const int* in_sizes, int n_in,
                              void* d_out, int out_size)
{
    (void)in_sizes; (void)n_in; (void)out_size;

    const float* x       = (const float*)d_in[0];
    const float* x_ref   = (const float*)d_in[1];
    const float* w_g     = (const float*)d_in[2];
    const float* b_g     = (const float*)d_in[3];
    const float* w_theta = (const float*)d_in[4];
    const float* b_theta = (const float*)d_in[5];
    const float* w_phi   = (const float*)d_in[6];
    const float* b_phi   = (const float*)d_in[7];
    const float* w_out   = (const float*)d_in[8];
    const float* b_out   = (const float*)d_in[9];
    float* out = (float*)d_out;

    __nv_bfloat16 *wb, *yb;
    float *theta, *gbuf, *phi, *pwpart, *pw;
    cudaGetSymbolAddress((void**)&wb,     g_wb);
    cudaGetSymbolAddress((void**)&theta,  g_theta);
    cudaGetSymbolAddress((void**)&gbuf,   g_g);
    cudaGetSymbolAddress((void**)&phi,    g_phi);
    cudaGetSymbolAddress((void**)&pwpart, g_pwpart);
    cudaGetSymbolAddress((void**)&pw,     g_pw);
    cudaGetSymbolAddress((void**)&yb,     g_yb);

    const int WSZ = CINT * CIN;
    __nv_bfloat16* wtb = wb + 0 * WSZ;
    __nv_bfloat16* wgb = wb + 1 * WSZ;
    __nv_bfloat16* wpb = wb + 2 * WSZ;
    __nv_bfloat16* wob = wb + 3 * WSZ;

    // weight conversions only (activations read as fp32 by bgemm_f32b)
    f2bf_kernel<<<WSZ / (256 * 8), 256>>>(w_theta, wtb, WSZ);
    f2bf_kernel<<<WSZ / (256 * 8), 256>>>(w_g,     wgb, WSZ);
    f2bf_kernel<<<WSZ / (256 * 8), 256>>>(w_phi,   wpb, WSZ);
    f2bf_kernel<<<WSZ / (256 * 8), 256>>>(w_out,   wob, WSZ);

    // 1x1 convs (tensor-core GEMMs, fp32 activations)
    dim3 blk(256);
    dim3 gg1(PP / 128, CINT / 128, NB);     // (72, 4, 4)
    bgemm_f32b<<<gg1, blk>>>(wtb, x,     b_theta, theta, CINT, CIN, PP);
    bgemm_f32b<<<gg1, blk>>>(wgb, x_ref, b_g,     gbuf,  CINT, CIN, PP);
    bgemm_f32b<<<gg1, blk>>>(wpb, x_ref, b_phi,   phi,   CINT, CIN, PP);

    // correlation partials (x-pair, f32x2) + softmax
    dim3 cg(WW / CTW, HH / CTH2, NB * CSPLIT);   // (3, 6, 8) = 144 blocks
    corr_kernel<<<cg, blk>>>(theta, phi, pwpart);
    softmax_kernel<<<(NB * PP) / 128, 128>>>(pwpart, pw);

    // assemble (x-pair, f32x2, bf16 output)
    dim3 ag(WW / CTW, HH / CTH2, NB * ASPLIT);   // (3, 6, 32) = 576 blocks
    assemble_kernel<<<ag, blk>>>(pw, gbuf, yb);

    // final conv + residual
    dim3 gg2(PP / 128, CIN / 128, NB);           // (72, 8, 4)
    bgemm_kernel<<<gg2, blk>>>(wob, yb, b_out, x, out, CIN, CINT, PP);
}

// round 8
// speedup vs baseline: 1.0592x; 1.0592x over previous
#include <cuda_runtime.h>
#include <cuda_bf16.h>
#include <math.h>
#include <stdint.h>

// Problem constants
#define NB    4
#define CIN   1024
#define CINT  512
#define HH    96
#define WW    96
#define PP    (HH * WW)      // 9216
#define DD    4
#define QQ    81
#define CSPLIT 2             // corr channel split
#define ASPLIT 8             // assemble channel split

// ---------------------------------------------------------------------------
// Scratch (device globals; no allocation allowed)
// ---------------------------------------------------------------------------
__device__ __align__(128) __nv_bfloat16 g_xb   [NB * CIN  * PP];
__device__ __align__(128) __nv_bfloat16 g_xrefb[NB * CIN  * PP];
__device__ __align__(128) __nv_bfloat16 g_wb   [4 * CINT * CIN];   // theta,g,phi,out
__device__ __align__(128) float g_theta [NB * CINT * PP];
__device__ __align__(128) float g_g     [NB * CINT * PP];
__device__ __align__(128) float g_phi   [NB * CINT * PP];
__device__ __align__(128) float g_pwpart[CSPLIT * NB * QQ * PP];
__device__ __align__(128) float g_pw    [NB * QQ * PP];
__device__ __align__(128) __nv_bfloat16 g_yb   [NB * CINT * PP];

// ---------------------------------------------------------------------------
// Helpers (legacy path: cp.async + ldmatrix + mma.sync; no tcgen05 — the
// toolchain targets sm_103 without the 'a' feature set)
// ---------------------------------------------------------------------------
__device__ __forceinline__ uint32_t sptr(const void* p) {
    return (uint32_t)__cvta_generic_to_shared(p);
}
__device__ __forceinline__ void cp16(uint32_t dst, const void* src) {
    asm volatile("cp.async.cg.shared.global [%0], [%1], 16;" :: "r"(dst), "l"(src));
}
__device__ __forceinline__ void cp_commit() {
    asm volatile("cp.async.commit_group;");
}
__device__ __forceinline__ void cp_wait0() {
    asm volatile("cp.async.wait_group 0;");
}
__device__ __forceinline__ void ldsmx4(uint32_t* r, uint32_t addr) {
    asm volatile("ldmatrix.sync.aligned.m8n8.x4.shared.b16 {%0,%1,%2,%3}, [%4];"
                 : "=r"(r[0]), "=r"(r[1]), "=r"(r[2]), "=r"(r[3]) : "r"(addr));
}
__device__ __forceinline__ void ldsmx4t(uint32_t* r, uint32_t addr) {
    asm volatile("ldmatrix.sync.aligned.m8n8.x4.trans.shared.b16 {%0,%1,%2,%3}, [%4];"
                 : "=r"(r[0]), "=r"(r[1]), "=r"(r[2]), "=r"(r[3]) : "r"(addr));
}
__device__ __forceinline__ void mma16816(float* c, const uint32_t* a, const uint32_t* b) {
    asm volatile("mma.sync.aligned.m16n8k16.row.col.f32.bf16.bf16.f32 "
                 "{%0,%1,%2,%3}, {%4,%5,%6,%7}, {%8,%9}, {%0,%1,%2,%3};"
                 : "+f"(c[0]), "+f"(c[1]), "+f"(c[2]), "+f"(c[3])
                 : "r"(a[0]), "r"(a[1]), "r"(a[2]), "r"(a[3]), "r"(b[0]), "r"(b[1]));
}

// Packed f32x2 (Blackwell base ISA): doubles fp32 FMA throughput.
__device__ __forceinline__ unsigned long long pk2(float a, float b) {
    unsigned long long r;
    asm("mov.b64 %0, {%1, %2};" : "=l"(r) : "f"(a), "f"(b));
    return r;
}
__device__ __forceinline__ void fma2(unsigned long long& d,
                                     unsigned long long a, unsigned long long b) {
    asm("fma.rn.f32x2 %0, %1, %2, %0;" : "+l"(d) : "l"(a), "l"(b));
}
__device__ __forceinline__ float2 upk(unsigned long long v) {
    float2 r;
    asm("mov.b64 {%0, %1}, %2;" : "=f"(r.x), "=f"(r.y) : "l"(v));
    return r;
}

// ---------------------------------------------------------------------------
// fp32 -> bf16 conversion (n multiple of 8)
// ---------------------------------------------------------------------------
__global__ void __launch_bounds__(256)
f2bf_kernel(const float* __restrict__ in, __nv_bfloat16* __restrict__ out, int n)
{
    int i = (blockIdx.x * 256 + threadIdx.x) * 8;
    if (i >= n) return;
    float4 v0 = *(const float4*)(in + i);
    float4 v1 = *(const float4*)(in + i + 4);
    __nv_bfloat162 o[4];
    o[0] = __floats2bfloat162_rn(v0.x, v0.y);
    o[1] = __floats2bfloat162_rn(v0.z, v0.w);
    o[2] = __floats2bfloat162_rn(v1.x, v1.y);
    o[3] = __floats2bfloat162_rn(v1.z, v1.w);
    *(uint4*)(out + i) = *(const uint4*)o;
}

// ---------------------------------------------------------------------------
// bf16 tensor-core GEMM (mma.sync):
// O[b][m][p] = sum_k W[m][k]*Z[b][k][p] + bias[m] (+ res[b][m][p])
// BM=BN=128, BK=32, 8 warps (2m x 4n), warp tile 64x32.  (round-5 version)
// ---------------------------------------------------------------------------
#define AS_STRIDE 40
#define BS_STRIDE 136
#define AS_ELEMS (128 * AS_STRIDE)
#define BS_ELEMS (32 * BS_STRIDE)
#define AS_BYTES (AS_ELEMS * 2)
#define BS_BYTES (BS_ELEMS * 2)

__global__ void __launch_bounds__(256)
bgemm_kernel(const __nv_bfloat16* __restrict__ W, const __nv_bfloat16* __restrict__ Z,
             const float* __restrict__ bias, const float* __restrict__ res,
             float* __restrict__ O, int M, int K, int P)
{
    __shared__ __align__(16) __nv_bfloat16 As[2 * AS_ELEMS];
    __shared__ __align__(16) __nv_bfloat16 Bs[2 * BS_ELEMS];

    const int b  = blockIdx.z;
    const __nv_bfloat16* Zb = Z + (size_t)b * K * P;
    float*       Ob = O + (size_t)b * M * P;
    const float* Rb = res ? res + (size_t)b * M * P : nullptr;

    const int m0 = blockIdx.y * 128;
    const int n0 = blockIdx.x * 128;
    const int tid  = threadIdx.x;
    const int lane = tid & 31;
    const int wid  = tid >> 5;
    const int wm = wid & 1;
    const int wn = wid >> 1;

    const uint32_t as0 = sptr(As);
    const uint32_t bs0 = sptr(Bs);

    const int a_r = tid >> 2;
    const int a_c = tid & 3;
    const int b_r = tid >> 4;
    const int b_c = tid & 15;

    float acc[4][4][4];
#pragma unroll
    for (int mt = 0; mt < 4; mt++)
#pragma unroll
        for (int nt = 0; nt < 4; nt++)
#pragma unroll
            for (int i = 0; i < 4; i++) acc[mt][nt][i] = 0.f;

    const int nk = K >> 5;

    {
        cp16(as0 + (uint32_t)((a_r)      * AS_STRIDE + a_c * 8) * 2, W  + (size_t)(m0 + a_r)      * K + a_c * 8);
        cp16(as0 + (uint32_t)((a_r + 64) * AS_STRIDE + a_c * 8) * 2, W  + (size_t)(m0 + a_r + 64) * K + a_c * 8);
        cp16(bs0 + (uint32_t)((b_r)      * BS_STRIDE + b_c * 8) * 2, Zb + (size_t)(b_r)      * P + n0 + b_c * 8);
        cp16(bs0 + (uint32_t)((b_r + 16) * BS_STRIDE + b_c * 8) * 2, Zb + (size_t)(b_r + 16) * P + n0 + b_c * 8);
        cp_commit();
    }

    int stage = 0;
    for (int kt = 0; kt < nk; kt++) {
        cp_wait0();
        __syncthreads();

        if (kt + 1 < nk) {
            const int k0 = (kt + 1) * 32;
            const uint32_t as = as0 + (stage ^ 1) * AS_BYTES;
            const uint32_t bs = bs0 + (stage ^ 1) * BS_BYTES;
            cp16(as + (uint32_t)((a_r)      * AS_STRIDE + a_c * 8) * 2, W  + (size_t)(m0 + a_r)      * K + k0 + a_c * 8);
            cp16(as + (uint32_t)((a_r + 64) * AS_STRIDE + a_c * 8) * 2, W  + (size_t)(m0 + a_r + 64) * K + k0 + a_c * 8);
            cp16(bs + (uint32_t)((b_r)      * BS_STRIDE + b_c * 8) * 2, Zb + (size_t)(k0 + b_r)      * P + n0 + b_c * 8);
            cp16(bs + (uint32_t)((b_r + 16) * BS_STRIDE + b_c * 8) * 2, Zb + (size_t)(k0 + b_r + 16) * P + n0 + b_c * 8);
            cp_commit();
        }

        const uint32_t as = as0 + stage * AS_BYTES;
        const uint32_t bs = bs0 + stage * BS_BYTES;

#pragma unroll
        for (int kk = 0; kk < 2; kk++) {
            const int k0 = kk * 16;
            uint32_t a[4][4];
            const uint32_t a_base = as + (uint32_t)(((wm * 64 + (lane & 15)) * AS_STRIDE) + k0 + (lane >> 4) * 8) * 2;
#pragma unroll
            for (int mt = 0; mt < 4; mt++)
                ldsmx4(a[mt], a_base + (uint32_t)(mt * 16 * AS_STRIDE) * 2);

            uint32_t bb[4][2];
            const uint32_t b_base = bs + (uint32_t)((k0 + (lane & 15)) * BS_STRIDE + wn * 32 + (lane >> 4) * 8) * 2;
            {
                uint32_t r[4];
                ldsmx4t(r, b_base);
                bb[0][0] = r[0]; bb[0][1] = r[1];
                bb[1][0] = r[2]; bb[1][1] = r[3];
                ldsmx4t(r, b_base + 16 * 2);
                bb[2][0] = r[0]; bb[2][1] = r[1];
                bb[3][0] = r[2]; bb[3][1] = r[3];
            }

#pragma unroll
            for (int mt = 0; mt < 4; mt++)
#pragma unroll
                for (int nt = 0; nt < 4; nt++)
                    mma16816(acc[mt][nt], a[mt], bb[nt]);
        }
        stage ^= 1;
        __syncthreads();
    }

#pragma unroll
    for (int mt = 0; mt < 4; mt++) {
        const int r0 = m0 + wm * 64 + mt * 16 + (lane >> 2);
        const int r1 = r0 + 8;
        const float bv0 = bias[r0];
        const float bv1 = bias[r1];
#pragma unroll
        for (int nt = 0; nt < 4; nt++) {
            const int col = n0 + wn * 32 + nt * 8 + (lane & 3) * 2;
            float2 v0 = make_float2(acc[mt][nt][0] + bv0, acc[mt][nt][1] + bv0);
            float2 v1 = make_float2(acc[mt][nt][2] + bv1, acc[mt][nt][3] + bv1);
            if (Rb) {
                float2 t0 = *(const float2*)&Rb[(size_t)r0 * P + col];
                float2 t1 = *(const float2*)&Rb[(size_t)r1 * P + col];
                v0.x += t0.x; v0.y += t0.y;
                v1.x += t1.x; v1.y += t1.y;
            }
            *(float2*)&Ob[(size_t)r0 * P + col] = v0;
            *(float2*)&Ob[(size_t)r1 * P + col] = v1;
        }
    }
}

// ---------------------------------------------------------------------------
// Correlation, x-pair blocking + packed f32x2 FMA.
// Tile 32(w) x 16(h); thread (tx,ty) owns pixels (ty, 2tx) and (ty, 2tx+1).
// ---------------------------------------------------------------------------
#define CTW 32
#define CTH2 16
#define CWW (CTW + 2 * DD)    // 40
#define CWH (CTH2 + 2 * DD)   // 24
#define CCH 8
#define CPB (CINT / CSPLIT)   // 256

__global__ void __launch_bounds__(256, 1)
corr_kernel(const float* __restrict__ theta,
            const float* __restrict__ phi,
            float* __restrict__ pwpart)
{
    __shared__ float th_s[CCH * CTH2 * CTW];   // 16 KB
    __shared__ float ph_s[CCH * CWH * CWW];    // 30 KB

    const int z  = blockIdx.z;
    const int b  = z >> 1;
    const int ci = z & 1;
    const int ch0 = ci * CPB;
    const int w0 = blockIdx.x * CTW;
    const int h0 = blockIdx.y * CTH2;
    const int tid = threadIdx.x;
    const int tx = tid & 15;          // 16 threads in x, 2 pixels each
    const int ty = tid >> 4;          // 0..15

    const float* thb = theta + (size_t)b * CINT * PP;
    const float* phb = phi   + (size_t)b * CINT * PP;

    unsigned long long accp[QQ];
#pragma unroll
    for (int q = 0; q < QQ; q++) accp[q] = 0ull;

    for (int c0 = ch0; c0 < ch0 + CPB; c0 += CCH) {
#pragma unroll
        for (int ii = 0; ii < (CCH * CTH2 * CTW) / 256; ii++) {
            const int i   = tid + ii * 256;
            const int cc  = i >> 9;
            const int rem = i & 511;
            th_s[i] = thb[(size_t)(c0 + cc) * PP + (h0 + (rem >> 5)) * WW + (w0 + (rem & 31))];
        }
#pragma unroll
        for (int ii = 0; ii < (CCH * CWH * CWW) / 256; ii++) {
            const int i   = tid + ii * 256;
            const int cc  = i / (CWH * CWW);
            const int rem = i % (CWH * CWW);
            const int r   = rem / CWW;
            const int col = rem % CWW;
            const int hh = h0 - DD + r;
            const int ww = w0 - DD + col;
            float v = 0.f;
            if (hh >= 0 && hh < HH && ww >= 0 && ww < WW)
                v = phb[(size_t)(c0 + cc) * PP + hh * WW + ww];
            ph_s[i] = v;
        }
        __syncthreads();

#pragma unroll
        for (int cc = 0; cc < CCH; cc++) {
            const float2 t2 = *(const float2*)&th_s[cc * (CTH2 * CTW) + ty * CTW + 2 * tx];
            const unsigned long long tp = pk2(t2.x, t2.y);
            const float* pr = &ph_s[cc * (CWH * CWW)];
#pragma unroll
            for (int dy = 0; dy < 9; dy++) {
                const float* row = &pr[(ty + dy) * CWW + 2 * tx];
                const float2 e0 = *(const float2*)&row[0];
                const float2 e1 = *(const float2*)&row[2];
                const float2 e2 = *(const float2*)&row[4];
                const float2 e3 = *(const float2*)&row[6];
                const float2 e4 = *(const float2*)&row[8];
                fma2(accp[dy * 9 + 0], tp, pk2(e0.x, e0.y));
                fma2(accp[dy * 9 + 1], tp, pk2(e0.y, e1.x));
                fma2(accp[dy * 9 + 2], tp, pk2(e1.x, e1.y));
                fma2(accp[dy * 9 + 3], tp, pk2(e1.y, e2.x));
                fma2(accp[dy * 9 + 4], tp, pk2(e2.x, e2.y));
                fma2(accp[dy * 9 + 5], tp, pk2(e2.y, e3.x));
                fma2(accp[dy * 9 + 6], tp, pk2(e3.x, e3.y));
                fma2(accp[dy * 9 + 7], tp, pk2(e3.y, e4.x));
                fma2(accp[dy * 9 + 8], tp, pk2(e4.x, e4.y));
            }
        }
        __syncthreads();
    }

    const int pixA = (h0 + ty) * WW + (w0 + 2 * tx);
    float* bp = pwpart + ((size_t)(ci * NB + b) * QQ) * PP;
#pragma unroll
    for (int q = 0; q < QQ; q++)
        *(float2*)&bp[(size_t)q * PP + pixA] = upk(accp[q]);
}

// ---------------------------------------------------------------------------
// Softmax over Q (sums 2 channel-split partials, applies scale)
// ---------------------------------------------------------------------------
__global__ void __launch_bounds__(128)
softmax_kernel(const float* __restrict__ part, float* __restrict__ pw)
{
    const int t = blockIdx.x * 128 + threadIdx.x;
    const int b = t / PP;
    const int pix = t - b * PP;
    const size_t qp = (size_t)QQ * PP;
    const float scale = 256.0f / sqrtf((float)WW) / (float)CINT;

    float v[QQ];
    float m = -1e30f;
#pragma unroll
    for (int q = 0; q < QQ; q++) {
        const size_t off = (size_t)q * PP + pix;
        float s = part[(size_t)(0 * NB + b) * qp + off]
                + part[(size_t)(1 * NB + b) * qp + off];
        v[q] = s * scale;
        m = fmaxf(m, v[q]);
    }
    float s = 0.f;
#pragma unroll
    for (int q = 0; q < QQ; q++) { v[q] = __expf(v[q] - m); s += v[q]; }
    const float inv = 1.0f / s;
    float* pwb = pw + (size_t)b * qp + pix;
#pragma unroll
    for (int q = 0; q < QQ; q++) pwb[(size_t)q * PP] = v[q] * inv;
}

// ---------------------------------------------------------------------------
// Assemble, x-pair blocking + packed f32x2: y = sum_q pw*g_window (bf16 out)
// ---------------------------------------------------------------------------
__global__ void __launch_bounds__(256, 1)
assemble_kernel(const float* __restrict__ pw,
                const float* __restrict__ g,
                __nv_bfloat16* __restrict__ y)
{
    __shared__ float gs[CCH * CWH * CWW];   // 30 KB

    const int z  = blockIdx.z;
    const int b  = z >> 3;
    const int c0base = (z & 7) * (CINT / ASPLIT); // 64 channels
    const int w0 = blockIdx.x * CTW;
    const int h0 = blockIdx.y * CTH2;
    const int tid = threadIdx.x;
    const int tx = tid & 15;
    const int ty = tid >> 4;

    const float* gb  = g  + (size_t)b * CINT * PP;
    const float* pwb = pw + (size_t)b * QQ * PP;
    __nv_bfloat16* yb = y + (size_t)b * CINT * PP;

    const int pixA = (h0 + ty) * WW + (w0 + 2 * tx);

    unsigned long long rp[QQ];
#pragma unroll
    for (int q = 0; q < QQ; q++) {
        const float2 v = *(const float2*)&pwb[(size_t)q * PP + pixA];
        rp[q] = pk2(v.x, v.y);
    }

    for (int c0 = c0base; c0 < c0base + CINT / ASPLIT; c0 += CCH) {
#pragma unroll
        for (int ii = 0; ii < (CCH * CWH * CWW) / 256; ii++) {
            const int i   = tid + ii * 256;
            const int cc  = i / (CWH * CWW);
            const int rem = i % (CWH * CWW);
            const int r   = rem / CWW;
            const int col = rem % CWW;
            const int hh = h0 - DD + r;
            const int ww = w0 - DD + col;
            float v = 0.f;
            if (hh >= 0 && hh < HH && ww >= 0 && ww < WW)
                v = gb[(size_t)(c0 + cc) * PP + hh * WW + ww];
            gs[i] = v;
        }
        __syncthreads();

#pragma unroll
        for (int cc = 0; cc < CCH; cc++) {
            const float* gr = &gs[cc * (CWH * CWW)];
            unsigned long long a2 = 0ull;
#pragma unroll
            for (int dy = 0; dy < 9; dy++) {
                const float* row = &gr[(ty + dy) * CWW + 2 * tx];
                const float2 e0 = *(const float2*)&row[0];
                const float2 e1 = *(const float2*)&row[2];
                const float2 e2 = *(const float2*)&row[4];
                const float2 e3 = *(const float2*)&row[6];
                const float2 e4 = *(const float2*)&row[8];
                fma2(a2, rp[dy * 9 + 0], pk2(e0.x, e0.y));
                fma2(a2, rp[dy * 9 + 1], pk2(e0.y, e1.x));
                fma2(a2, rp[dy * 9 + 2], pk2(e1.x, e1.y));
                fma2(a2, rp[dy * 9 + 3], pk2(e1.y, e2.x));
                fma2(a2, rp[dy * 9 + 4], pk2(e2.x, e2.y));
                fma2(a2, rp[dy * 9 + 5], pk2(e2.y, e3.x));
                fma2(a2, rp[dy * 9 + 6], pk2(e3.x, e3.y));
                fma2(a2, rp[dy * 9 + 7], pk2(e3.y, e4.x));
                fma2(a2, rp[dy * 9 + 8], pk2(e4.x, e4.y));
            }
            const float2 r = upk(a2);
            *(__nv_bfloat162*)&yb[(size_t)(c0 + cc) * PP + pixA] =
                __floats2bfloat162_rn(r.x, r.y);
        }
        __syncthreads();
    }
}

// ---------------------------------------------------------------------------
// Launch
// ---------------------------------------------------------------------------
extern "C" void kernel_launch(void* const* d_in, const int* in_sizes, int n_in,
                              void* d_out, int out_size)
{
    (void)in_sizes; (void)n_in; (void)out_size;

    const float* x       = (const float*)d_in[0];
    const float* x_ref   = (const float*)d_in[1];
    const float* w_g     = (const float*)d_in[2];
    const float* b_g     = (const float*)d_in[3];
    const float* w_theta = (const float*)d_in[4];
    const float* b_theta = (const float*)d_in[5];
    const float* w_phi   = (const float*)d_in[6];
    const float* b_phi   = (const float*)d_in[7];
    const float* w_out   = (const float*)d_in[8];
    const float* b_out   = (const float*)d_in[9];
    float* out = (float*)d_out;

    __nv_bfloat16 *xb, *xrefb, *wb, *yb;
    float *theta, *gbuf, *phi, *pwpart, *pw;
    cudaGetSymbolAddress((void**)&xb,     g_xb);
    cudaGetSymbolAddress((void**)&xrefb,  g_xrefb);
    cudaGetSymbolAddress((void**)&wb,     g_wb);
    cudaGetSymbolAddress((void**)&theta,  g_theta);
    cudaGetSymbolAddress((void**)&gbuf,   g_g);
    cudaGetSymbolAddress((void**)&phi,    g_phi);
    cudaGetSymbolAddress((void**)&pwpart, g_pwpart);
    cudaGetSymbolAddress((void**)&pw,     g_pw);
    cudaGetSymbolAddress((void**)&yb,     g_yb);

    const int WSZ = CINT * CIN;
    __nv_bfloat16* wtb = wb + 0 * WSZ;
    __nv_bfloat16* wgb = wb + 1 * WSZ;
    __nv_bfloat16* wpb = wb + 2 * WSZ;
    __nv_bfloat16* wob = wb + 3 * WSZ;

    // conversions
    const int nx = NB * CIN * PP;
    f2bf_kernel<<<nx / (256 * 8), 256>>>(x,     xb,    nx);
    f2bf_kernel<<<nx / (256 * 8), 256>>>(x_ref, xrefb, nx);
    f2bf_kernel<<<WSZ / (256 * 8), 256>>>(w_theta, wtb, WSZ);
    f2bf_kernel<<<WSZ / (256 * 8), 256>>>(w_g,     wgb, WSZ);
    f2bf_kernel<<<WSZ / (256 * 8), 256>>>(w_phi,   wpb, WSZ);
    f2bf_kernel<<<WSZ / (256 * 8), 256>>>(w_out,   wob, WSZ);

    // 1x1 convs (tensor-core GEMMs, all-bf16 cp.async path)
    dim3 blk(256);
    dim3 gg1(PP / 128, CINT / 128, NB);     // (72, 4, 4)
    bgemm_kernel<<<gg1, blk>>>(wtb, xb,    b_theta, nullptr, theta, CINT, CIN, PP);
    bgemm_kernel<<<gg1, blk>>>(wgb, xrefb, b_g,     nullptr, gbuf,  CINT, CIN, PP);
    bgemm_kernel<<<gg1, blk>>>(wpb, xrefb, b_phi,   nullptr, phi,   CINT, CIN, PP);

    // correlation partials (x-pair, f32x2) + softmax
    dim3 cg(WW / CTW, HH / CTH2, NB * CSPLIT);   // (3, 6, 8) = 144 blocks
    corr_kernel<<<cg, blk>>>(theta, phi, pwpart);
    softmax_kernel<<<(NB * PP) / 128, 128>>>(pwpart, pw);

    // assemble (x-pair, f32x2, bf16 output)
    dim3 ag(WW / CTW, HH / CTH2, NB * ASPLIT);   // (3, 6, 32) = 576 blocks
    assemble_kernel<<<ag, blk>>>(pw, gbuf, yb);

    // final conv + residual
    dim3 gg2(PP / 128, CIN / 128, NB);           // (72, 8, 4)
    bgemm_kernel<<<gg2, blk>>>(wob, yb, b_out, x, out, CIN, CINT, PP);
}